// round 8
// baseline (speedup 1.0000x reference)
#include <cuda_runtime.h>
#include <cuda_bf16.h>
#include <math.h>
#include <stdint.h>

// Problem constants
#define BATCH 32
#define CIN   8
#define COUT  8
#define KK    4
#define DIN   16
#define DOUT  16
#define SS    32
#define EPSV  1e-5f

// ---------------- scratch ---------------------------------------------------
__device__ float g_votes[(size_t)BATCH * 1024 * 1024];
__device__ float g_pooled[(size_t)BATCH * COUT * 2 * DOUT * SS * SS];
__device__ float g_routed[(size_t)BATCH * COUT * DOUT * SS * SS];
__device__ float g_graw[(size_t)BATCH * COUT * DOUT * SS * SS];
__device__ double g_bnsum[COUT];
__device__ double g_bnsq[COUT];
__device__ float  g_bnmu[COUT];
__device__ float  g_bninv[COUT];
// bf16 conv weights, remapped: [c][oc 128][k 296]: cols 0..143 hi, 144..287 lo
#define CV_PITCH 296
__device__ uint16_t g_Aw[(size_t)8 * 128 * CV_PITCH];
// folded einsum bias bveff[o][m][d]
__device__ float g_bveff[COUT * 32 * DOUT];

// ---------------- helpers ---------------------------------------------------
__device__ __forceinline__ uint32_t smem_u32(const void* p) {
    uint32_t a;
    asm("{ .reg .u64 t; cvta.to.shared.u64 t, %1; cvt.u32.u64 %0, t; }"
        : "=r"(a) : "l"(p));
    return a;
}
__device__ __forceinline__ void ldsm4(uint32_t* r, uint32_t addr) {
    asm volatile("ldmatrix.sync.aligned.m8n8.x4.shared.b16 {%0,%1,%2,%3}, [%4];"
                 : "=r"(r[0]), "=r"(r[1]), "=r"(r[2]), "=r"(r[3]) : "r"(addr));
}
__device__ __forceinline__ void mma16816(float* c, const uint32_t* a, const uint32_t* b) {
    asm volatile("mma.sync.aligned.m16n8k16.row.col.f32.bf16.bf16.f32 "
                 "{%0,%1,%2,%3}, {%4,%5,%6,%7}, {%8,%9}, {%0,%1,%2,%3};"
                 : "+f"(c[0]), "+f"(c[1]), "+f"(c[2]), "+f"(c[3])
                 : "r"(a[0]), "r"(a[1]), "r"(a[2]), "r"(a[3]), "r"(b[0]), "r"(b[1]));
}

// ---------------- kernel P: prep (weight remap + bias fold + BN zero) ------
__global__ void k_prep(const float* __restrict__ Wt, const float* __restrict__ bt,
                       const float* __restrict__ Wv, const float* __restrict__ bv)
{
    int blk = blockIdx.x;
    if (blk < 8) {
        int c = blk;
        uint16_t* dst = g_Aw + (size_t)c * 128 * CV_PITCH;
        for (int i = threadIdx.x; i < 128 * 144; i += blockDim.x) {
            int row = i / 144, k = i % 144;
            int ic = k / 9, s = k % 9;
            int col = s * 16 + ic;
            float v = Wt[(size_t)(c * 128 + row) * 144 + k];
            __nv_bfloat16 h = __float2bfloat16(v);
            __nv_bfloat16 l = __float2bfloat16(v - __bfloat162float(h));
            dst[(size_t)row * CV_PITCH + col] = *(uint16_t*)&h;
            dst[(size_t)row * CV_PITCH + 144 + col] = *(uint16_t*)&l;
        }
        for (int i = threadIdx.x; i < 128 * 8; i += blockDim.x) {
            int row = i >> 3, col = 288 + (i & 7);
            dst[(size_t)row * CV_PITCH + col] = 0;
        }
    } else {
        if (threadIdx.x < COUT) {
            g_bnsum[threadIdx.x] = 0.0;
            g_bnsq[threadIdx.x] = 0.0;
        }
        // bveff[o][m][d] = bv[o][m] + sum_c Wv[o][m][c] * bt[c*128 + o*16 + d]
        for (int i = threadIdx.x; i < COUT * 32 * DOUT; i += blockDim.x) {
            int d = i & 15, m = (i >> 4) & 31, o = i >> 9;
            float a = bv[o * 32 + m];
#pragma unroll
            for (int c = 0; c < 8; c++)
                a += Wv[o * 256 + m * 8 + c] * bt[c * 128 + o * 16 + d];
            g_bveff[i] = a;
        }
    }
}

// ---------------- kernel 1: conv via mma.sync bf16-split -------------------
// CTA = (pxtile 0..7 [128 px = 4 y-rows], c 0..7, b 0..31). 256 threads.
#define CV_ROWB  (CV_PITCH * 2)                 // 592 bytes per row
#define SM_A     1024
#define SM_B     (SM_A + 128 * CV_ROWB)         // 76800
#define SM_SRAW  (SM_B + 128 * CV_ROWB)         // 152576
#define SM_ST    (SM_SRAW + 13056)              // 165632
#define CONV_SMEM (SM_ST + 13056)               // 178688

__global__ __launch_bounds__(256, 1) void k_conv_mma(const float* __restrict__ caps)
{
    extern __shared__ char smc[];
    uint32_t sb = smem_u32(smc);
    int tid = threadIdx.x, wid = tid >> 5, lane = tid & 31;
    int pxt = blockIdx.x;     // y0 = pxt*4
    int c   = blockIdx.y;
    int b   = blockIdx.z;

    // A copy (pre-remapped bf16 weights): 75776 B = 4736 uint4
    {
        const uint4* As = (const uint4*)(g_Aw + (size_t)c * 128 * CV_PITCH);
        uint4* Ad = (uint4*)(smc + SM_A);
        for (int i = tid; i < 4736; i += 256) Ad[i] = As[i];
    }
    // stage_raw [ic][yy 0..5][xx 0..33], zero-padded border
    {
        float* sraw = (float*)(smc + SM_SRAW);
        const float* cin = caps + (size_t)b * 16384;
        int y0 = pxt * 4;
        for (int i = tid; i < 16 * 204; i += 256) {
            int ic = i / 204, rem = i % 204;
            int yy = rem / 34, xx = rem % 34;
            int y = y0 - 1 + yy, x = xx - 1;
            float v = 0.f;
            if ((unsigned)y < 32u && (unsigned)x < 32u) v = cin[ic * 1024 + y * 32 + x];
            sraw[i] = v;
        }
    }
    __syncthreads();
    // transpose -> stage_t [pos 0..203][ic 0..15]
    {
        float* sraw = (float*)(smc + SM_SRAW);
        float* st   = (float*)(smc + SM_ST);
        for (int i = tid; i < 16 * 204; i += 256) {
            int pos = i >> 4, ic = i & 15;
            st[pos * 16 + ic] = sraw[ic * 204 + pos];
        }
    }
    __syncthreads();
    // B build: 128 px rows x 9 s-chunks; row layout [px][k 296] hi@s*16+ic, lo@144+
    {
        const float* st = (const float*)(smc + SM_ST);
        uint16_t* Bp = (uint16_t*)(smc + SM_B);
        for (int i = tid; i < 128 * 9; i += 256) {
            int p = i / 9, s = i % 9;
            int yl = p >> 5, x = p & 31;
            int ky = s / 3, kx = s % 3;
            const float* src = &st[((yl + ky) * 34 + (x + kx)) * 16];
            uint32_t hi[8], lo[8];
#pragma unroll
            for (int j = 0; j < 8; j++) {
                float v0 = src[2 * j], v1 = src[2 * j + 1];
                __nv_bfloat16 h0 = __float2bfloat16(v0);
                __nv_bfloat16 h1 = __float2bfloat16(v1);
                __nv_bfloat16 l0 = __float2bfloat16(v0 - __bfloat162float(h0));
                __nv_bfloat16 l1 = __float2bfloat16(v1 - __bfloat162float(h1));
                hi[j] = ((uint32_t)(*(uint16_t*)&h1) << 16) | (*(uint16_t*)&h0);
                lo[j] = ((uint32_t)(*(uint16_t*)&l1) << 16) | (*(uint16_t*)&l0);
            }
            uint16_t* rowp = Bp + (size_t)p * CV_PITCH;
            *(uint4*)(rowp + s * 16)       = make_uint4(hi[0], hi[1], hi[2], hi[3]);
            *(uint4*)(rowp + s * 16 + 8)   = make_uint4(hi[4], hi[5], hi[6], hi[7]);
            *(uint4*)(rowp + 144 + s * 16)     = make_uint4(lo[0], lo[1], lo[2], lo[3]);
            *(uint4*)(rowp + 144 + s * 16 + 8) = make_uint4(lo[4], lo[5], lo[6], lo[7]);
        }
    }
    __syncthreads();

    // --- MMA mainloop: warp tile 32 oc x 64 px ---
    int OCB = (wid & 3) * 32;
    int PXB = (wid >> 2) * 64;
    uint32_t Ab = sb + SM_A, Bb = sb + SM_B;
    uint32_t aBase = Ab + (uint32_t)(OCB + (lane & 15)) * CV_ROWB + ((lane >> 4) * 8) * 2;
    uint32_t bBase = Bb + (uint32_t)(PXB + (lane & 7) + ((lane >> 4) << 3)) * CV_ROWB +
                     (((lane >> 3) & 1) * 8) * 2;

    float acc[2][8][4];
#pragma unroll
    for (int mf = 0; mf < 2; mf++)
#pragma unroll
        for (int f = 0; f < 8; f++)
#pragma unroll
            for (int q = 0; q < 4; q++) acc[mf][f][q] = 0.f;

#pragma unroll
    for (int s = 0; s < 9; s++) {
        uint32_t kh = (uint32_t)(s * 16) * 2;
        uint32_t kl = (uint32_t)(144 + s * 16) * 2;
        uint32_t ah[2][4], al[2][4];
        ldsm4(ah[0], aBase + kh);
        ldsm4(ah[1], aBase + 16 * CV_ROWB + kh);
        ldsm4(al[0], aBase + kl);
        ldsm4(al[1], aBase + 16 * CV_ROWB + kl);
        uint32_t bh[16], bl[16];
#pragma unroll
        for (int q = 0; q < 4; q++) {
            ldsm4(&bh[q * 4], bBase + (uint32_t)(q * 16) * CV_ROWB + kh);
            ldsm4(&bl[q * 4], bBase + (uint32_t)(q * 16) * CV_ROWB + kl);
        }
#pragma unroll
        for (int mf = 0; mf < 2; mf++) {
#pragma unroll
            for (int f = 0; f < 8; f++) {
                mma16816(acc[mf][f], ah[mf], &bh[f * 2]);
                mma16816(acc[mf][f], ah[mf], &bl[f * 2]);
                mma16816(acc[mf][f], al[mf], &bh[f * 2]);
            }
        }
    }

    // epilogue
    {
        int g = lane >> 2, tq = lane & 3;
        size_t vbase = ((size_t)b * 8 + c) * 131072 + (size_t)pxt * 128;
#pragma unroll
        for (int mf = 0; mf < 2; mf++) {
#pragma unroll
            for (int f = 0; f < 8; f++) {
                int row = OCB + mf * 16 + g;
                int col = PXB + f * 8 + tq * 2;
                float2 v0; v0.x = acc[mf][f][0]; v0.y = acc[mf][f][1];
                float2 v1; v1.x = acc[mf][f][2]; v1.y = acc[mf][f][3];
                *(float2*)&g_votes[vbase + (size_t)row * 1024 + col] = v0;
                *(float2*)&g_votes[vbase + (size_t)(row + 8) * 1024 + col] = v1;
            }
        }
    }
}

// ---------------- kernel 2: einsum + pooling + routing (x4 vectorized) -----
// one thread per (d, 4-site quad). grid (16, o, b), 256 thr.
__global__ __launch_bounds__(256) void k_values(const float* __restrict__ Wv)
{
    __shared__ float sWv[256];      // 32 m x 8 c
    __shared__ float sbe[512];      // bveff[m][d]
    int b = blockIdx.z, o = blockIdx.y;
    sWv[threadIdx.x] = Wv[o * 256 + threadIdx.x];
    sbe[threadIdx.x] = g_bveff[o * 512 + threadIdx.x];
    sbe[threadIdx.x + 256] = g_bveff[o * 512 + 256 + threadIdx.x];
    __syncthreads();

    int idx = blockIdx.x * 256 + threadIdx.x;   // 0..4095
    int d  = idx >> 8;
    int s0 = (idx & 255) * 4;

    const float* vb = g_votes + (size_t)b * 1048576 + (size_t)o * 16384 +
                      (size_t)d * 1024 + s0;
    float4 vc4[8];
#pragma unroll
    for (int c = 0; c < 8; c++) vc4[c] = *(const float4*)(vb + (size_t)c * 131072);
    const float* vcp = (const float*)vc4;

    float rpm[4], rps[4], rrt[4];
#pragma unroll
    for (int j = 0; j < 4; j++) {
        float vcj[8];
#pragma unroll
        for (int c = 0; c < 8; c++) vcj[c] = vcp[c * 4 + j];

        float pmax = -3.0e38f, psum = 0.f;
        float num = 0.f, den = 0.f;
#pragma unroll
        for (int cin = 0; cin < 8; cin++) {
            float vals[4];
#pragma unroll
            for (int kc = 0; kc < 4; kc++) {
                int m = kc * 8 + cin;
                float a = sbe[m * 16 + d];
#pragma unroll
                for (int c = 0; c < 8; c++) a += sWv[m * 8 + c] * vcj[c];
                vals[kc] = a;
                pmax = fmaxf(pmax, a);
                psum += a;
            }
            float mn = 0.25f * (vals[0] + vals[1] + vals[2] + vals[3]);
            float d0 = vals[0] - mn, d1 = vals[1] - mn;
            float d2 = vals[2] - mn, d3 = vals[3] - mn;
            float var = 0.25f * (d0 * d0 + d1 * d1 + d2 * d2 + d3 * d3);
            float r = rsqrtf(fmaxf(var, 1e-30f));
            num += r * mn;
            den += r;
        }
        rpm[j] = pmax;
        rps[j] = psum * (1.f / 32.f);
        rrt[j] = num / den;
    }

    size_t pbase = ((size_t)b * 8 + o) * 32768 + (size_t)d * 1024 + s0;
    size_t rbase = ((size_t)b * 8 + o) * 16384 + (size_t)d * 1024 + s0;
    *(float4*)&g_pooled[pbase]         = make_float4(rpm[0], rpm[1], rpm[2], rpm[3]);
    *(float4*)&g_pooled[pbase + 16384] = make_float4(rps[0], rps[1], rps[2], rps[3]);
    *(float4*)&g_routed[rbase]         = make_float4(rrt[0], rrt[1], rrt[2], rrt[3]);
}

// ---------------- kernel 3: 3x3x3 gate conv + BN (d-split, occ 2) ----------
#define GP2_PITCH 36
#define GP2_PLANE (34 * GP2_PITCH)      // 1224
#define GP2_CH    (10 * GP2_PLANE)      // 12240
#define GP2_TOT   (2 * GP2_CH)          // 24480 floats = 97920 B
#define GATE_SMEM (GP2_TOT * 4)

__global__ __launch_bounds__(512, 2) void k_gate(const float* __restrict__ Ws)
{
    extern __shared__ float sp[];
    __shared__ float sws[54];
    __shared__ double redA[16], redB[16];
    int blk = blockIdx.x;          // b*16 + o*2 + dh
    int dh = blk & 1;
    int o  = (blk >> 1) & 7;
    int bo = blk >> 1;             // b*8 + o
    int tid = threadIdx.x;

    for (int i = tid; i < GP2_TOT; i += 512) sp[i] = 0.f;
    if (tid < 54) sws[tid] = Ws[tid];
    __syncthreads();

    const float* src = g_pooled + (size_t)bo * 32768;
    int dbase = dh * 8 - 1;
    for (int i = tid; i < 2 * 10 * 1024; i += 512) {
        int px = i & 1023;
        int j  = (i >> 10) % 10;
        int p  = i / 10240;
        int dd = dbase + j;
        if ((unsigned)dd < 16u) {
            int u = px >> 5, v = px & 31;
            sp[p * GP2_CH + j * GP2_PLANE + (u + 1) * GP2_PITCH + (v + 1)] =
                src[p * 16384 + dd * 1024 + px];
        }
    }
    __syncthreads();

    double ls = 0.0, lq = 0.0;
    for (int k = 0; k < 4; k++) {
        int q = k * 512 + tid;            // quad: dloc*256 + u*8 + vq
        int v0 = (q & 7) * 4;
        int u  = (q >> 3) & 31;
        int dloc = q >> 8;
        float a0 = 0.f, a1 = 0.f, a2 = 0.f, a3 = 0.f;
#pragma unroll
        for (int p = 0; p < 2; p++) {
#pragma unroll
            for (int kd = 0; kd < 3; kd++) {
#pragma unroll
                for (int ku = 0; ku < 3; ku++) {
                    const float* rp = &sp[p * GP2_CH + (dloc + kd) * GP2_PLANE +
                                          (u + ku) * GP2_PITCH + v0];
                    float4 f = *(const float4*)rp;
                    float i4 = rp[4], i5 = rp[5];
                    const float* w = &sws[p * 27 + kd * 9 + ku * 3];
                    float w0 = w[0], w1 = w[1], w2 = w[2];
                    a0 += w0 * f.x + w1 * f.y + w2 * f.z;
                    a1 += w0 * f.y + w1 * f.z + w2 * f.w;
                    a2 += w0 * f.z + w1 * f.w + w2 * i4;
                    a3 += w0 * f.w + w1 * i4 + w2 * i5;
                }
            }
        }
        float4 r; r.x = a0; r.y = a1; r.z = a2; r.w = a3;
        *(float4*)&g_graw[(size_t)bo * 16384 + (size_t)(dh * 8 + dloc) * 1024 +
                          (size_t)u * 32 + v0] = r;
        ls += (double)(a0 + a1 + a2 + a3);
        lq += (double)a0 * a0 + (double)a1 * a1 + (double)a2 * a2 + (double)a3 * a3;
    }

    for (int off = 16; off; off >>= 1) {
        ls += __shfl_down_sync(0xffffffffu, ls, off);
        lq += __shfl_down_sync(0xffffffffu, lq, off);
    }
    int wid = tid >> 5, lane = tid & 31;
    if (lane == 0) { redA[wid] = ls; redB[wid] = lq; }
    __syncthreads();
    if (tid < 32) {
        double a = (tid < 16) ? redA[tid] : 0.0;
        double qq = (tid < 16) ? redB[tid] : 0.0;
        for (int off = 8; off; off >>= 1) {
            a += __shfl_down_sync(0xffffffffu, a, off);
            qq += __shfl_down_sync(0xffffffffu, qq, off);
        }
        if (tid == 0) {
            atomicAdd(&g_bnsum[o], a);
            atomicAdd(&g_bnsq[o], qq);
        }
    }
}

// ---------------- kernel 4: BN finalize ------------------------------------
__global__ void k_bnfin() {
    int o = threadIdx.x;
    if (o < COUT) {
        double N = (double)BATCH * DOUT * SS * SS;
        double mu = g_bnsum[o] / N;
        double var = g_bnsq[o] / N - mu * mu;
        g_bnmu[o]  = (float)mu;
        g_bninv[o] = (float)(1.0 / sqrt(var + (double)EPSV));
    }
}

// ---------------- kernel 5: scale + LayerNorm + transposed store -----------
__global__ __launch_bounds__(512) void k_final(
    const float* __restrict__ bng, const float* __restrict__ bnb,
    const float* __restrict__ lng, const float* __restrict__ lnb,
    float* __restrict__ out)
{
    __shared__ double redA[16], redB[16];
    __shared__ float bc[2];
    int blk = blockIdx.x;
    int b = blk >> 3, o = blk & 7;
    int tid = threadIdx.x;

    float mu = g_bnmu[o], inv = g_bninv[o];
    float ga = bng[0], be = bnb[0];
    const float4* gr = (const float4*)(g_graw   + (size_t)blk * 16384);
    const float4* rt = (const float4*)(g_routed + (size_t)blk * 16384);

    float4 xv[8];
    double ls = 0.0, lq = 0.0;
#pragma unroll
    for (int k = 0; k < 8; k++) {
        int i = k * 512 + tid;
        float4 g4 = gr[i];
        float4 r4 = rt[i];
        float4 x;
        {
            float g = (g4.x - mu) * inv * ga + be;
            x.x = r4.x * (1.f + 1.f / (1.f + __expf(-g)));
            g = (g4.y - mu) * inv * ga + be;
            x.y = r4.y * (1.f + 1.f / (1.f + __expf(-g)));
            g = (g4.z - mu) * inv * ga + be;
            x.z = r4.z * (1.f + 1.f / (1.f + __expf(-g)));
            g = (g4.w - mu) * inv * ga + be;
            x.w = r4.w * (1.f + 1.f / (1.f + __expf(-g)));
        }
        xv[k] = x;
        ls += (double)(x.x + x.y) + (double)(x.z + x.w);
        lq += (double)x.x * x.x + (double)x.y * x.y +
              (double)x.z * x.z + (double)x.w * x.w;
    }
    for (int off = 16; off; off >>= 1) {
        ls += __shfl_down_sync(0xffffffffu, ls, off);
        lq += __shfl_down_sync(0xffffffffu, lq, off);
    }
    int wid = tid >> 5, lane = tid & 31;
    if (lane == 0) { redA[wid] = ls; redB[wid] = lq; }
    __syncthreads();
    if (tid < 32) {
        double a = (tid < 16) ? redA[tid] : 0.0;
        double q = (tid < 16) ? redB[tid] : 0.0;
        for (int off = 8; off; off >>= 1) {
            a += __shfl_down_sync(0xffffffffu, a, off);
            q += __shfl_down_sync(0xffffffffu, q, off);
        }
        if (tid == 0) {
            double N = 16384.0;
            double mean = a / N;
            double var = q / N - mean * mean;
            bc[0] = (float)mean;
            bc[1] = (float)(1.0 / sqrt(var + (double)EPSV));
        }
    }
    __syncthreads();
    float mean = bc[0], rstd = bc[1];
    float4* ob = (float4*)(out + ((size_t)o * BATCH + b) * 16384);
    const float4* lg4 = (const float4*)lng;
    const float4* lb4 = (const float4*)lnb;
#pragma unroll
    for (int k = 0; k < 8; k++) {
        int i = k * 512 + tid;
        float4 x = xv[k];
        float4 g = lg4[i];
        float4 bb = lb4[i];
        float4 r;
        r.x = (x.x - mean) * rstd * g.x + bb.x;
        r.y = (x.y - mean) * rstd * g.y + bb.y;
        r.z = (x.z - mean) * rstd * g.z + bb.z;
        r.w = (x.w - mean) * rstd * g.w + bb.w;
        ob[i] = r;
    }
}

// ---------------- launch ----------------------------------------------------
extern "C" void kernel_launch(void* const* d_in, const int* in_sizes, int n_in,
                              void* d_out, int out_size)
{
    const float* caps = (const float*)d_in[0];
    const float* Wt   = (const float*)d_in[1];
    const float* bt   = (const float*)d_in[2];
    const float* Wv   = (const float*)d_in[3];
    const float* bv   = (const float*)d_in[4];
    const float* Ws   = (const float*)d_in[5];
    const float* bng  = (const float*)d_in[6];
    const float* bnb  = (const float*)d_in[7];
    const float* lng  = (const float*)d_in[8];
    const float* lnb  = (const float*)d_in[9];
    float* out = (float*)d_out;

    cudaFuncSetAttribute(k_conv_mma, cudaFuncAttributeMaxDynamicSharedMemorySize, CONV_SMEM);
    cudaFuncSetAttribute(k_gate, cudaFuncAttributeMaxDynamicSharedMemorySize, GATE_SMEM);

    k_prep<<<9, 256>>>(Wt, bt, Wv, bv);

    dim3 gconv(8, 8, BATCH);
    k_conv_mma<<<gconv, 256, CONV_SMEM>>>(caps);

    dim3 gval(16, COUT, BATCH);
    k_values<<<gval, 256>>>(Wv);

    k_gate<<<BATCH * COUT * 2, 512, GATE_SMEM>>>(Ws);

    k_bnfin<<<1, 8>>>();

    k_final<<<BATCH * COUT, 512>>>(bng, bnb, lng, lnb, out);

    (void)in_sizes; (void)n_in; (void)out_size;
}

// round 9
// speedup vs baseline: 1.3259x; 1.3259x over previous
#include <cuda_runtime.h>
#include <cuda_bf16.h>
#include <math.h>
#include <stdint.h>

// Problem constants
#define BATCH 32
#define CIN   8
#define COUT  8
#define KK    4
#define DIN   16
#define DOUT  16
#define SS    32
#define EPSV  1e-5f

// ---------------- scratch ---------------------------------------------------
__device__ float g_votes[(size_t)BATCH * 1024 * 1024];
__device__ float g_pooled[(size_t)BATCH * COUT * 2 * DOUT * SS * SS];
__device__ float g_routed[(size_t)BATCH * COUT * DOUT * SS * SS];
__device__ float g_graw[(size_t)BATCH * COUT * DOUT * SS * SS];
__device__ double g_bnsum[COUT];
__device__ double g_bnsq[COUT];
__device__ float  g_bnmu[COUT];
__device__ float  g_bninv[COUT];
// bf16 conv weights, remapped: [c][oc 128][k 296]: cols 0..143 hi, 144..287 lo
#define CV_PITCH 296
__device__ uint16_t g_Aw[(size_t)8 * 128 * CV_PITCH];
// folded einsum bias bveff[o][m][d]
__device__ float g_bveff[COUT * 32 * DOUT];

// ---------------- helpers ---------------------------------------------------
__device__ __forceinline__ uint32_t smem_u32(const void* p) {
    uint32_t a;
    asm("{ .reg .u64 t; cvta.to.shared.u64 t, %1; cvt.u32.u64 %0, t; }"
        : "=r"(a) : "l"(p));
    return a;
}
__device__ __forceinline__ void ldsm4(uint32_t* r, uint32_t addr) {
    asm volatile("ldmatrix.sync.aligned.m8n8.x4.shared.b16 {%0,%1,%2,%3}, [%4];"
                 : "=r"(r[0]), "=r"(r[1]), "=r"(r[2]), "=r"(r[3]) : "r"(addr));
}
__device__ __forceinline__ void mma16816(float* c, const uint32_t* a, const uint32_t* b) {
    asm volatile("mma.sync.aligned.m16n8k16.row.col.f32.bf16.bf16.f32 "
                 "{%0,%1,%2,%3}, {%4,%5,%6,%7}, {%8,%9}, {%0,%1,%2,%3};"
                 : "+f"(c[0]), "+f"(c[1]), "+f"(c[2]), "+f"(c[3])
                 : "r"(a[0]), "r"(a[1]), "r"(a[2]), "r"(a[3]), "r"(b[0]), "r"(b[1]));
}

// ---------------- kernel P: prep (weight remap + bias fold + BN zero) ------
__global__ void k_prep(const float* __restrict__ Wt, const float* __restrict__ bt,
                       const float* __restrict__ Wv, const float* __restrict__ bv)
{
    int blk = blockIdx.x;
    if (blk < 8) {
        int c = blk;
        uint16_t* dst = g_Aw + (size_t)c * 128 * CV_PITCH;
        for (int i = threadIdx.x; i < 128 * 144; i += blockDim.x) {
            int row = i / 144, k = i % 144;
            int ic = k / 9, s = k % 9;
            int col = s * 16 + ic;
            float v = Wt[(size_t)(c * 128 + row) * 144 + k];
            __nv_bfloat16 h = __float2bfloat16(v);
            __nv_bfloat16 l = __float2bfloat16(v - __bfloat162float(h));
            dst[(size_t)row * CV_PITCH + col] = *(uint16_t*)&h;
            dst[(size_t)row * CV_PITCH + 144 + col] = *(uint16_t*)&l;
        }
        for (int i = threadIdx.x; i < 128 * 8; i += blockDim.x) {
            int row = i >> 3, col = 288 + (i & 7);
            dst[(size_t)row * CV_PITCH + col] = 0;
        }
    } else {
        if (threadIdx.x < COUT) {
            g_bnsum[threadIdx.x] = 0.0;
            g_bnsq[threadIdx.x] = 0.0;
        }
        // bveff[o][m][d] = bv[o][m] + sum_c Wv[o][m][c] * bt[c*128 + o*16 + d]
        for (int i = threadIdx.x; i < COUT * 32 * DOUT; i += blockDim.x) {
            int d = i & 15, m = (i >> 4) & 31, o = i >> 9;
            float a = bv[o * 32 + m];
#pragma unroll
            for (int c = 0; c < 8; c++)
                a += Wv[o * 256 + m * 8 + c] * bt[c * 128 + o * 16 + d];
            g_bveff[i] = a;
        }
    }
}

// ---------------- kernel 1: conv via mma.sync bf16-split, A from gmem ------
// CTA = (pxtile 0..7 [128 px = 4 y-rows], c 0..7, b 0..31). 256 threads, occ 2.
// smem holds ONLY the B tile + staging; A fragments load straight from g_Aw.
#define CV_ROWB  (CV_PITCH * 2)                 // 592 bytes per row
#define SM_B     1024
#define SM_SRAW  (SM_B + 128 * CV_ROWB)         // 76800
#define SM_ST    (SM_SRAW + 13056)              // 89856
#define CONV_SMEM (SM_ST + 13056)               // 102912 -> 2 CTAs/SM

__global__ __launch_bounds__(256, 2) void k_conv_mma(const float* __restrict__ caps)
{
    extern __shared__ char smc[];
    uint32_t sb = smem_u32(smc);
    int tid = threadIdx.x, wid = tid >> 5, lane = tid & 31;
    int pxt = blockIdx.x;     // y0 = pxt*4
    int c   = blockIdx.y;
    int b   = blockIdx.z;

    // stage_raw [ic][yy 0..5][xx 0..33], zero-padded border
    {
        float* sraw = (float*)(smc + SM_SRAW);
        const float* cin = caps + (size_t)b * 16384;
        int y0 = pxt * 4;
        for (int i = tid; i < 16 * 204; i += 256) {
            int ic = i / 204, rem = i % 204;
            int yy = rem / 34, xx = rem % 34;
            int y = y0 - 1 + yy, x = xx - 1;
            float v = 0.f;
            if ((unsigned)y < 32u && (unsigned)x < 32u) v = cin[ic * 1024 + y * 32 + x];
            sraw[i] = v;
        }
    }
    __syncthreads();
    // transpose -> stage_t [pos 0..203][ic 0..15]
    {
        float* sraw = (float*)(smc + SM_SRAW);
        float* st   = (float*)(smc + SM_ST);
        for (int i = tid; i < 16 * 204; i += 256) {
            int pos = i >> 4, ic = i & 15;
            st[pos * 16 + ic] = sraw[ic * 204 + pos];
        }
    }
    __syncthreads();
    // B build: 128 px rows x 9 s-chunks; row layout [px][k 296] hi@s*16+ic, lo@144+
    {
        const float* st = (const float*)(smc + SM_ST);
        uint16_t* Bp = (uint16_t*)(smc + SM_B);
        for (int i = tid; i < 128 * 9; i += 256) {
            int p = i / 9, s = i % 9;
            int yl = p >> 5, x = p & 31;
            int ky = s / 3, kx = s % 3;
            const float* src = &st[((yl + ky) * 34 + (x + kx)) * 16];
            uint32_t hi[8], lo[8];
#pragma unroll
            for (int j = 0; j < 8; j++) {
                float v0 = src[2 * j], v1 = src[2 * j + 1];
                __nv_bfloat16 h0 = __float2bfloat16(v0);
                __nv_bfloat16 h1 = __float2bfloat16(v1);
                __nv_bfloat16 l0 = __float2bfloat16(v0 - __bfloat162float(h0));
                __nv_bfloat16 l1 = __float2bfloat16(v1 - __bfloat162float(h1));
                hi[j] = ((uint32_t)(*(uint16_t*)&h1) << 16) | (*(uint16_t*)&h0);
                lo[j] = ((uint32_t)(*(uint16_t*)&l1) << 16) | (*(uint16_t*)&l0);
            }
            uint16_t* rowp = Bp + (size_t)p * CV_PITCH;
            *(uint4*)(rowp + s * 16)       = make_uint4(hi[0], hi[1], hi[2], hi[3]);
            *(uint4*)(rowp + s * 16 + 8)   = make_uint4(hi[4], hi[5], hi[6], hi[7]);
            *(uint4*)(rowp + 144 + s * 16)     = make_uint4(lo[0], lo[1], lo[2], lo[3]);
            *(uint4*)(rowp + 144 + s * 16 + 8) = make_uint4(lo[4], lo[5], lo[6], lo[7]);
        }
    }
    __syncthreads();

    // --- MMA mainloop: warp tile 32 oc x 64 px; A frags via LDG from g_Aw ---
    int OCB = (wid & 3) * 32;
    int PXB = (wid >> 2) * 64;
    uint32_t Bb = sb + SM_B;
    uint32_t bBase = Bb + (uint32_t)(PXB + (lane & 7) + ((lane >> 4) << 3)) * CV_ROWB +
                     (((lane >> 3) & 1) * 8) * 2;

    // per-thread A fragment addressing (mma m16n8k16 A layout):
    // reg0: row=base+(lane>>2), col=k+(lane&3)*2 ; reg1: row+8 ; reg2: col+8 ; reg3: both
    const uint16_t* Ab = g_Aw + (size_t)c * 128 * CV_PITCH +
                         (size_t)(OCB + (lane >> 2)) * CV_PITCH + (lane & 3) * 2;

    float acc[2][8][4];
#pragma unroll
    for (int mf = 0; mf < 2; mf++)
#pragma unroll
        for (int f = 0; f < 8; f++)
#pragma unroll
            for (int q = 0; q < 4; q++) acc[mf][f][q] = 0.f;

#pragma unroll
    for (int s = 0; s < 9; s++) {
        int kh = s * 16;
        int kl = 144 + s * 16;
        uint32_t ah[2][4], al[2][4];
#pragma unroll
        for (int mf = 0; mf < 2; mf++) {
            const uint16_t* ap = Ab + (size_t)(mf * 16) * CV_PITCH;
            ah[mf][0] = *(const uint32_t*)(ap + kh);
            ah[mf][1] = *(const uint32_t*)(ap + 8 * CV_PITCH + kh);
            ah[mf][2] = *(const uint32_t*)(ap + kh + 8);
            ah[mf][3] = *(const uint32_t*)(ap + 8 * CV_PITCH + kh + 8);
            al[mf][0] = *(const uint32_t*)(ap + kl);
            al[mf][1] = *(const uint32_t*)(ap + 8 * CV_PITCH + kl);
            al[mf][2] = *(const uint32_t*)(ap + kl + 8);
            al[mf][3] = *(const uint32_t*)(ap + 8 * CV_PITCH + kl + 8);
        }
        uint32_t bh[16], bl[16];
#pragma unroll
        for (int q = 0; q < 4; q++) {
            ldsm4(&bh[q * 4], bBase + (uint32_t)(q * 16) * CV_ROWB + (uint32_t)kh * 2);
            ldsm4(&bl[q * 4], bBase + (uint32_t)(q * 16) * CV_ROWB + (uint32_t)kl * 2);
        }
#pragma unroll
        for (int mf = 0; mf < 2; mf++) {
#pragma unroll
            for (int f = 0; f < 8; f++) {
                mma16816(acc[mf][f], ah[mf], &bh[f * 2]);
                mma16816(acc[mf][f], ah[mf], &bl[f * 2]);
                mma16816(acc[mf][f], al[mf], &bh[f * 2]);
            }
        }
    }

    // epilogue
    {
        int g = lane >> 2, tq = lane & 3;
        size_t vbase = ((size_t)b * 8 + c) * 131072 + (size_t)pxt * 128;
#pragma unroll
        for (int mf = 0; mf < 2; mf++) {
#pragma unroll
            for (int f = 0; f < 8; f++) {
                int row = OCB + mf * 16 + g;
                int col = PXB + f * 8 + tq * 2;
                float2 v0; v0.x = acc[mf][f][0]; v0.y = acc[mf][f][1];
                float2 v1; v1.x = acc[mf][f][2]; v1.y = acc[mf][f][3];
                *(float2*)&g_votes[vbase + (size_t)row * 1024 + col] = v0;
                *(float2*)&g_votes[vbase + (size_t)(row + 8) * 1024 + col] = v1;
            }
        }
    }
}

// ---------------- kernel 2: einsum + pooling + routing (rsqrt softmax) -----
// one thread per (site, d). grid (64, o, b), 256 thr.  (R7 form)
__global__ __launch_bounds__(256) void k_values(const float* __restrict__ Wv)
{
    __shared__ float sWv[256];      // 32 m x 8 c
    __shared__ float sbe[512];      // bveff[m][d]
    int b = blockIdx.z, o = blockIdx.y;
    sWv[threadIdx.x] = Wv[o * 256 + threadIdx.x];
    sbe[threadIdx.x] = g_bveff[o * 512 + threadIdx.x];
    sbe[threadIdx.x + 256] = g_bveff[o * 512 + 256 + threadIdx.x];
    __syncthreads();

    int i = blockIdx.x * 256 + threadIdx.x;   // 0..16383
    int s = i & 1023;
    int d = i >> 10;

    const float* vb = g_votes + (size_t)b * 1048576 + (size_t)o * 16384 +
                      (size_t)d * 1024 + s;
    float vc[8];
#pragma unroll
    for (int c = 0; c < 8; c++) vc[c] = vb[(size_t)c * 131072];

    float pmax = -3.0e38f, psum = 0.f;
    float num = 0.f, den = 0.f;
#pragma unroll
    for (int cin = 0; cin < 8; cin++) {
        float vals[4];
#pragma unroll
        for (int kc = 0; kc < 4; kc++) {
            int m = kc * 8 + cin;
            float a = sbe[m * 16 + d];
#pragma unroll
            for (int c = 0; c < 8; c++) a += sWv[m * 8 + c] * vc[c];
            vals[kc] = a;
            pmax = fmaxf(pmax, a);
            psum += a;
        }
        float mn = 0.25f * (vals[0] + vals[1] + vals[2] + vals[3]);
        float d0 = vals[0] - mn, d1 = vals[1] - mn;
        float d2 = vals[2] - mn, d3 = vals[3] - mn;
        float var = 0.25f * (d0 * d0 + d1 * d1 + d2 * d2 + d3 * d3);
        float r = rsqrtf(fmaxf(var, 1e-30f));
        num += r * mn;
        den += r;
    }

    size_t pbase = ((size_t)b * 8 + o) * 32768;
    size_t rbase = ((size_t)b * 8 + o) * 16384;
    g_pooled[pbase + (size_t)d * 1024 + s]         = pmax;
    g_pooled[pbase + 16384 + (size_t)d * 1024 + s] = psum * (1.f / 32.f);
    g_routed[rbase + (size_t)d * 1024 + s]         = num / den;
}

// ---------------- kernel 3: 3x3x3 gate conv + BN (d-split, occ 2) ----------
#define GP2_PITCH 36
#define GP2_PLANE (34 * GP2_PITCH)      // 1224
#define GP2_CH    (10 * GP2_PLANE)      // 12240
#define GP2_TOT   (2 * GP2_CH)          // 24480 floats = 97920 B
#define GATE_SMEM (GP2_TOT * 4)

__global__ __launch_bounds__(512, 2) void k_gate(const float* __restrict__ Ws)
{
    extern __shared__ float sp[];
    __shared__ float sws[54];
    __shared__ double redA[16], redB[16];
    int blk = blockIdx.x;          // b*16 + o*2 + dh
    int dh = blk & 1;
    int o  = (blk >> 1) & 7;
    int bo = blk >> 1;             // b*8 + o
    int tid = threadIdx.x;

    for (int i = tid; i < GP2_TOT; i += 512) sp[i] = 0.f;
    if (tid < 54) sws[tid] = Ws[tid];
    __syncthreads();

    const float* src = g_pooled + (size_t)bo * 32768;
    int dbase = dh * 8 - 1;
    for (int i = tid; i < 2 * 10 * 1024; i += 512) {
        int px = i & 1023;
        int j  = (i >> 10) % 10;
        int p  = i / 10240;
        int dd = dbase + j;
        if ((unsigned)dd < 16u) {
            int u = px >> 5, v = px & 31;
            sp[p * GP2_CH + j * GP2_PLANE + (u + 1) * GP2_PITCH + (v + 1)] =
                src[p * 16384 + dd * 1024 + px];
        }
    }
    __syncthreads();

    double ls = 0.0, lq = 0.0;
    for (int k = 0; k < 4; k++) {
        int q = k * 512 + tid;            // quad: dloc*256 + u*8 + vq
        int v0 = (q & 7) * 4;
        int u  = (q >> 3) & 31;
        int dloc = q >> 8;
        float a0 = 0.f, a1 = 0.f, a2 = 0.f, a3 = 0.f;
#pragma unroll
        for (int p = 0; p < 2; p++) {
#pragma unroll
            for (int kd = 0; kd < 3; kd++) {
#pragma unroll
                for (int ku = 0; ku < 3; ku++) {
                    const float* rp = &sp[p * GP2_CH + (dloc + kd) * GP2_PLANE +
                                          (u + ku) * GP2_PITCH + v0];
                    float4 f = *(const float4*)rp;
                    float i4 = rp[4], i5 = rp[5];
                    const float* w = &sws[p * 27 + kd * 9 + ku * 3];
                    float w0 = w[0], w1 = w[1], w2 = w[2];
                    a0 += w0 * f.x + w1 * f.y + w2 * f.z;
                    a1 += w0 * f.y + w1 * f.z + w2 * f.w;
                    a2 += w0 * f.z + w1 * f.w + w2 * i4;
                    a3 += w0 * f.w + w1 * i4 + w2 * i5;
                }
            }
        }
        float4 r; r.x = a0; r.y = a1; r.z = a2; r.w = a3;
        *(float4*)&g_graw[(size_t)bo * 16384 + (size_t)(dh * 8 + dloc) * 1024 +
                          (size_t)u * 32 + v0] = r;
        ls += (double)(a0 + a1 + a2 + a3);
        lq += (double)a0 * a0 + (double)a1 * a1 + (double)a2 * a2 + (double)a3 * a3;
    }

    for (int off = 16; off; off >>= 1) {
        ls += __shfl_down_sync(0xffffffffu, ls, off);
        lq += __shfl_down_sync(0xffffffffu, lq, off);
    }
    int wid = tid >> 5, lane = tid & 31;
    if (lane == 0) { redA[wid] = ls; redB[wid] = lq; }
    __syncthreads();
    if (tid < 32) {
        double a = (tid < 16) ? redA[tid] : 0.0;
        double qq = (tid < 16) ? redB[tid] : 0.0;
        for (int off = 8; off; off >>= 1) {
            a += __shfl_down_sync(0xffffffffu, a, off);
            qq += __shfl_down_sync(0xffffffffu, qq, off);
        }
        if (tid == 0) {
            atomicAdd(&g_bnsum[o], a);
            atomicAdd(&g_bnsq[o], qq);
        }
    }
}

// ---------------- kernel 4: BN finalize ------------------------------------
__global__ void k_bnfin() {
    int o = threadIdx.x;
    if (o < COUT) {
        double N = (double)BATCH * DOUT * SS * SS;
        double mu = g_bnsum[o] / N;
        double var = g_bnsq[o] / N - mu * mu;
        g_bnmu[o]  = (float)mu;
        g_bninv[o] = (float)(1.0 / sqrt(var + (double)EPSV));
    }
}

// ---------------- kernel 5: scale + LayerNorm + transposed store (R7 form) -
__global__ __launch_bounds__(512) void k_final(
    const float* __restrict__ bng, const float* __restrict__ bnb,
    const float* __restrict__ lng, const float* __restrict__ lnb,
    float* __restrict__ out)
{
    __shared__ double redA[16], redB[16];
    __shared__ float bc[2];
    int blk = blockIdx.x;
    int b = blk >> 3, o = blk & 7;
    int tid = threadIdx.x;

    float mu = g_bnmu[o], inv = g_bninv[o];
    float ga = bng[0], be = bnb[0];
    const float* gr = g_graw   + (size_t)blk * 16384;
    const float* rt = g_routed + (size_t)blk * 16384;

    float xv[32];
    double ls = 0.0, lq = 0.0;
#pragma unroll
    for (int k = 0; k < 32; k++) {
        int i = k * 512 + tid;
        float g = (gr[i] - mu) * inv * ga + be;
        float sc = 1.f / (1.f + __expf(-g));
        float x = rt[i] * (1.f + sc);
        xv[k] = x;
        ls += x;
        lq += (double)x * x;
    }
    for (int off = 16; off; off >>= 1) {
        ls += __shfl_down_sync(0xffffffffu, ls, off);
        lq += __shfl_down_sync(0xffffffffu, lq, off);
    }
    int wid = tid >> 5, lane = tid & 31;
    if (lane == 0) { redA[wid] = ls; redB[wid] = lq; }
    __syncthreads();
    if (tid < 32) {
        double a = (tid < 16) ? redA[tid] : 0.0;
        double q = (tid < 16) ? redB[tid] : 0.0;
        for (int off = 8; off; off >>= 1) {
            a += __shfl_down_sync(0xffffffffu, a, off);
            q += __shfl_down_sync(0xffffffffu, q, off);
        }
        if (tid == 0) {
            double N = 16384.0;
            double mean = a / N;
            double var = q / N - mean * mean;
            bc[0] = (float)mean;
            bc[1] = (float)(1.0 / sqrt(var + (double)EPSV));
        }
    }
    __syncthreads();
    float mean = bc[0], rstd = bc[1];
    float* ob = out + ((size_t)o * BATCH + b) * 16384;
#pragma unroll
    for (int k = 0; k < 32; k++) {
        int i = k * 512 + tid;
        ob[i] = (xv[k] - mean) * rstd * lng[i] + lnb[i];
    }
}

// ---------------- launch ----------------------------------------------------
extern "C" void kernel_launch(void* const* d_in, const int* in_sizes, int n_in,
                              void* d_out, int out_size)
{
    const float* caps = (const float*)d_in[0];
    const float* Wt   = (const float*)d_in[1];
    const float* bt   = (const float*)d_in[2];
    const float* Wv   = (const float*)d_in[3];
    const float* bv   = (const float*)d_in[4];
    const float* Ws   = (const float*)d_in[5];
    const float* bng  = (const float*)d_in[6];
    const float* bnb  = (const float*)d_in[7];
    const float* lng  = (const float*)d_in[8];
    const float* lnb  = (const float*)d_in[9];
    float* out = (float*)d_out;

    cudaFuncSetAttribute(k_conv_mma, cudaFuncAttributeMaxDynamicSharedMemorySize, CONV_SMEM);
    cudaFuncSetAttribute(k_gate, cudaFuncAttributeMaxDynamicSharedMemorySize, GATE_SMEM);

    k_prep<<<9, 256>>>(Wt, bt, Wv, bv);

    dim3 gconv(8, 8, BATCH);
    k_conv_mma<<<gconv, 256, CONV_SMEM>>>(caps);

    dim3 gval(64, COUT, BATCH);
    k_values<<<gval, 256>>>(Wv);

    k_gate<<<BATCH * COUT * 2, 512, GATE_SMEM>>>(Ws);

    k_bnfin<<<1, 8>>>();

    k_final<<<BATCH * COUT, 512>>>(bng, bnb, lng, lnb, out);

    (void)in_sizes; (void)n_in; (void)out_size;
}

// round 13
// speedup vs baseline: 1.3502x; 1.0184x over previous
#include <cuda_runtime.h>
#include <cuda_bf16.h>
#include <math.h>
#include <stdint.h>

// Problem constants
#define BATCH 32
#define CIN   8
#define COUT  8
#define KK    4
#define DIN   16
#define DOUT  16
#define SS    32
#define EPSV  1e-5f

// ---------------- scratch ---------------------------------------------------
__device__ float g_votes[(size_t)BATCH * 1024 * 1024];
__device__ float g_pooled[(size_t)BATCH * COUT * 2 * DOUT * SS * SS];
__device__ float g_routed[(size_t)BATCH * COUT * DOUT * SS * SS];
__device__ float g_graw[(size_t)BATCH * COUT * DOUT * SS * SS];
__device__ double g_bnsum[COUT];
__device__ double g_bnsq[COUT];
__device__ float  g_bnmu[COUT];
__device__ float  g_bninv[COUT];
// bf16 conv weights, remapped: [c][oc 128][k 296]: cols 0..143 hi, 144..287 lo
#define CV_PITCH 296
__device__ uint16_t g_Aw[(size_t)8 * 128 * CV_PITCH];
// folded einsum bias bveff[o][m][d]
__device__ float g_bveff[COUT * 32 * DOUT];

// ---------------- helpers ---------------------------------------------------
__device__ __forceinline__ uint32_t smem_u32(const void* p) {
    uint32_t a;
    asm("{ .reg .u64 t; cvta.to.shared.u64 t, %1; cvt.u32.u64 %0, t; }"
        : "=r"(a) : "l"(p));
    return a;
}
__device__ __forceinline__ void ldsm4(uint32_t* r, uint32_t addr) {
    asm volatile("ldmatrix.sync.aligned.m8n8.x4.shared.b16 {%0,%1,%2,%3}, [%4];"
                 : "=r"(r[0]), "=r"(r[1]), "=r"(r[2]), "=r"(r[3]) : "r"(addr));
}
__device__ __forceinline__ void mma16816(float* c, const uint32_t* a, const uint32_t* b) {
    asm volatile("mma.sync.aligned.m16n8k16.row.col.f32.bf16.bf16.f32 "
                 "{%0,%1,%2,%3}, {%4,%5,%6,%7}, {%8,%9}, {%0,%1,%2,%3};"
                 : "+f"(c[0]), "+f"(c[1]), "+f"(c[2]), "+f"(c[3])
                 : "r"(a[0]), "r"(a[1]), "r"(a[2]), "r"(a[3]), "r"(b[0]), "r"(b[1]));
}

// ---------------- kernel P: prep (weight remap + bias fold + BN zero) ------
__global__ void k_prep(const float* __restrict__ Wt, const float* __restrict__ bt,
                       const float* __restrict__ Wv, const float* __restrict__ bv)
{
    int blk = blockIdx.x;
    if (blk < 8) {
        int c = blk;
        uint16_t* dst = g_Aw + (size_t)c * 128 * CV_PITCH;
        for (int i = threadIdx.x; i < 128 * 144; i += blockDim.x) {
            int row = i / 144, k = i % 144;
            int ic = k / 9, s = k % 9;
            int col = s * 16 + ic;
            float v = Wt[(size_t)(c * 128 + row) * 144 + k];
            __nv_bfloat16 h = __float2bfloat16(v);
            __nv_bfloat16 l = __float2bfloat16(v - __bfloat162float(h));
            dst[(size_t)row * CV_PITCH + col] = *(uint16_t*)&h;
            dst[(size_t)row * CV_PITCH + 144 + col] = *(uint16_t*)&l;
        }
        for (int i = threadIdx.x; i < 128 * 8; i += blockDim.x) {
            int row = i >> 3, col = 288 + (i & 7);
            dst[(size_t)row * CV_PITCH + col] = 0;
        }
    } else {
        if (threadIdx.x < COUT) {
            g_bnsum[threadIdx.x] = 0.0;
            g_bnsq[threadIdx.x] = 0.0;
        }
        // bveff[o][m][d] = bv[o][m] + sum_c Wv[o][m][c] * bt[c*128 + o*16 + d]
        for (int i = threadIdx.x; i < COUT * 32 * DOUT; i += blockDim.x) {
            int d = i & 15, m = (i >> 4) & 31, o = i >> 9;
            float a = bv[o * 32 + m];
#pragma unroll
            for (int c = 0; c < 8; c++)
                a += Wv[o * 256 + m * 8 + c] * bt[c * 128 + o * 16 + d];
            g_bveff[i] = a;
        }
    }
}

// ---------------- kernel 1: conv via mma.sync bf16-split, c-loop -----------
// CTA = (pxtile 0..7 [128 px], b 0..31) = 256 CTAs. B tile built ONCE,
// reused for all 8 c (weights stream from gmem). 256 threads, occ 2.
#define CV_ROWB  (CV_PITCH * 2)                 // 592 bytes per row
#define SM_B     1024
#define SM_SRAW  (SM_B + 128 * CV_ROWB)         // 76800
#define SM_ST    (SM_SRAW + 13056)              // 89856
#define CONV_SMEM (SM_ST + 13056)               // 102912 -> 2 CTAs/SM

__global__ __launch_bounds__(256, 2) void k_conv_mma(const float* __restrict__ caps)
{
    extern __shared__ char smc[];
    uint32_t sb = smem_u32(smc);
    int tid = threadIdx.x, wid = tid >> 5, lane = tid & 31;
    int pxt = blockIdx.x;     // y0 = pxt*4
    int b   = blockIdx.y;

    // stage_raw [ic][yy 0..5][xx 0..33], zero-padded border
    {
        float* sraw = (float*)(smc + SM_SRAW);
        const float* cin = caps + (size_t)b * 16384;
        int y0 = pxt * 4;
        for (int i = tid; i < 16 * 204; i += 256) {
            int ic = i / 204, rem = i % 204;
            int yy = rem / 34, xx = rem % 34;
            int y = y0 - 1 + yy, x = xx - 1;
            float v = 0.f;
            if ((unsigned)y < 32u && (unsigned)x < 32u) v = cin[ic * 1024 + y * 32 + x];
            sraw[i] = v;
        }
    }
    __syncthreads();
    // transpose -> stage_t [pos 0..203][ic 0..15]
    {
        float* sraw = (float*)(smc + SM_SRAW);
        float* st   = (float*)(smc + SM_ST);
        for (int i = tid; i < 16 * 204; i += 256) {
            int pos = i >> 4, ic = i & 15;
            st[pos * 16 + ic] = sraw[ic * 204 + pos];
        }
    }
    __syncthreads();
    // B build: 128 px rows x 9 s-chunks; row layout [px][k 296] hi@s*16+ic, lo@144+
    {
        const float* st = (const float*)(smc + SM_ST);
        uint16_t* Bp = (uint16_t*)(smc + SM_B);
        for (int i = tid; i < 128 * 9; i += 256) {
            int p = i / 9, s = i % 9;
            int yl = p >> 5, x = p & 31;
            int ky = s / 3, kx = s % 3;
            const float* src = &st[((yl + ky) * 34 + (x + kx)) * 16];
            uint32_t hi[8], lo[8];
#pragma unroll
            for (int j = 0; j < 8; j++) {
                float v0 = src[2 * j], v1 = src[2 * j + 1];
                __nv_bfloat16 h0 = __float2bfloat16(v0);
                __nv_bfloat16 h1 = __float2bfloat16(v1);
                __nv_bfloat16 l0 = __float2bfloat16(v0 - __bfloat162float(h0));
                __nv_bfloat16 l1 = __float2bfloat16(v1 - __bfloat162float(h1));
                hi[j] = ((uint32_t)(*(uint16_t*)&h1) << 16) | (*(uint16_t*)&h0);
                lo[j] = ((uint32_t)(*(uint16_t*)&l1) << 16) | (*(uint16_t*)&l0);
            }
            uint16_t* rowp = Bp + (size_t)p * CV_PITCH;
            *(uint4*)(rowp + s * 16)       = make_uint4(hi[0], hi[1], hi[2], hi[3]);
            *(uint4*)(rowp + s * 16 + 8)   = make_uint4(hi[4], hi[5], hi[6], hi[7]);
            *(uint4*)(rowp + 144 + s * 16)     = make_uint4(lo[0], lo[1], lo[2], lo[3]);
            *(uint4*)(rowp + 144 + s * 16 + 8) = make_uint4(lo[4], lo[5], lo[6], lo[7]);
        }
    }
    __syncthreads();

    // --- per-c MMA mainloops: warp tile 32 oc x 64 px; A via LDG -----------
    int OCB = (wid & 3) * 32;
    int PXB = (wid >> 2) * 64;
    uint32_t Bb = sb + SM_B;
    uint32_t bBase = Bb + (uint32_t)(PXB + (lane & 7) + ((lane >> 4) << 3)) * CV_ROWB +
                     (((lane >> 3) & 1) * 8) * 2;
    const uint16_t* AbT = g_Aw + (size_t)(OCB + (lane >> 2)) * CV_PITCH + (lane & 3) * 2;

    for (int c = 0; c < 8; c++) {
        const uint16_t* Ab = AbT + (size_t)c * 128 * CV_PITCH;

        float acc[2][8][4];
#pragma unroll
        for (int mf = 0; mf < 2; mf++)
#pragma unroll
            for (int f = 0; f < 8; f++)
#pragma unroll
                for (int q = 0; q < 4; q++) acc[mf][f][q] = 0.f;

#pragma unroll
        for (int s = 0; s < 9; s++) {
            int kh = s * 16;
            int kl = 144 + s * 16;
            uint32_t ah[2][4], al[2][4];
#pragma unroll
            for (int mf = 0; mf < 2; mf++) {
                const uint16_t* ap = Ab + (size_t)(mf * 16) * CV_PITCH;
                ah[mf][0] = *(const uint32_t*)(ap + kh);
                ah[mf][1] = *(const uint32_t*)(ap + 8 * CV_PITCH + kh);
                ah[mf][2] = *(const uint32_t*)(ap + kh + 8);
                ah[mf][3] = *(const uint32_t*)(ap + 8 * CV_PITCH + kh + 8);
                al[mf][0] = *(const uint32_t*)(ap + kl);
                al[mf][1] = *(const uint32_t*)(ap + 8 * CV_PITCH + kl);
                al[mf][2] = *(const uint32_t*)(ap + kl + 8);
                al[mf][3] = *(const uint32_t*)(ap + 8 * CV_PITCH + kl + 8);
            }
            uint32_t bh[16], bl[16];
#pragma unroll
            for (int q = 0; q < 4; q++) {
                ldsm4(&bh[q * 4], bBase + (uint32_t)(q * 16) * CV_ROWB + (uint32_t)kh * 2);
                ldsm4(&bl[q * 4], bBase + (uint32_t)(q * 16) * CV_ROWB + (uint32_t)kl * 2);
            }
#pragma unroll
            for (int mf = 0; mf < 2; mf++) {
#pragma unroll
                for (int f = 0; f < 8; f++) {
                    mma16816(acc[mf][f], ah[mf], &bh[f * 2]);
                    mma16816(acc[mf][f], ah[mf], &bl[f * 2]);
                    mma16816(acc[mf][f], al[mf], &bh[f * 2]);
                }
            }
        }

        // epilogue for this c
        int g = lane >> 2, tq = lane & 3;
        size_t vbase = ((size_t)b * 8 + c) * 131072 + (size_t)pxt * 128;
#pragma unroll
        for (int mf = 0; mf < 2; mf++) {
#pragma unroll
            for (int f = 0; f < 8; f++) {
                int row = OCB + mf * 16 + g;
                int col = PXB + f * 8 + tq * 2;
                float2 v0; v0.x = acc[mf][f][0]; v0.y = acc[mf][f][1];
                float2 v1; v1.x = acc[mf][f][2]; v1.y = acc[mf][f][3];
                *(float2*)&g_votes[vbase + (size_t)row * 1024 + col] = v0;
                *(float2*)&g_votes[vbase + (size_t)(row + 8) * 1024 + col] = v1;
            }
        }
    }
}

// ---------------- kernel 2: einsum + pooling + routing (rsqrt softmax) -----
// one thread per (site, d). grid (64, o, b), 256 thr.
__global__ __launch_bounds__(256) void k_values(const float* __restrict__ Wv)
{
    __shared__ float sWv[256];      // 32 m x 8 c
    __shared__ float sbe[512];      // bveff[m][d]
    int b = blockIdx.z, o = blockIdx.y;
    sWv[threadIdx.x] = Wv[o * 256 + threadIdx.x];
    sbe[threadIdx.x] = g_bveff[o * 512 + threadIdx.x];
    sbe[threadIdx.x + 256] = g_bveff[o * 512 + 256 + threadIdx.x];
    __syncthreads();

    int i = blockIdx.x * 256 + threadIdx.x;   // 0..16383
    int s = i & 1023;
    int d = i >> 10;

    const float* vb = g_votes + (size_t)b * 1048576 + (size_t)o * 16384 +
                      (size_t)d * 1024 + s;
    float vc[8];
#pragma unroll
    for (int c = 0; c < 8; c++) vc[c] = vb[(size_t)c * 131072];

    float pmax = -3.0e38f, psum = 0.f;
    float num = 0.f, den = 0.f;
#pragma unroll
    for (int cin = 0; cin < 8; cin++) {
        float vals[4];
#pragma unroll
        for (int kc = 0; kc < 4; kc++) {
            int m = kc * 8 + cin;
            float a = sbe[m * 16 + d];
#pragma unroll
            for (int c = 0; c < 8; c++) a += sWv[m * 8 + c] * vc[c];
            vals[kc] = a;
            pmax = fmaxf(pmax, a);
            psum += a;
        }
        float mn = 0.25f * (vals[0] + vals[1] + vals[2] + vals[3]);
        float d0 = vals[0] - mn, d1 = vals[1] - mn;
        float d2 = vals[2] - mn, d3 = vals[3] - mn;
        float var = 0.25f * (d0 * d0 + d1 * d1 + d2 * d2 + d3 * d3);
        float r = rsqrtf(fmaxf(var, 1e-30f));
        num += r * mn;
        den += r;
    }

    size_t pbase = ((size_t)b * 8 + o) * 32768;
    size_t rbase = ((size_t)b * 8 + o) * 16384;
    g_pooled[pbase + (size_t)d * 1024 + s]         = pmax;
    g_pooled[pbase + 16384 + (size_t)d * 1024 + s] = psum * (1.f / 32.f);
    g_routed[rbase + (size_t)d * 1024 + s]         = num / den;
}

// ---------------- kernel 3: gate conv + BN (d-split, weight-hoisted) -------
#define GP2_PITCH 36
#define GP2_PLANE (34 * GP2_PITCH)      // 1224
#define GP2_CH    (10 * GP2_PLANE)      // 12240
#define GP2_TOT   (2 * GP2_CH)          // 24480 floats = 97920 B
#define GATE_SMEM (GP2_TOT * 4)

__global__ __launch_bounds__(512, 2) void k_gate(const float* __restrict__ Ws)
{
    extern __shared__ float sp[];
    __shared__ float sws[54];
    __shared__ double redA[16], redB[16];
    int blk = blockIdx.x;          // b*16 + o*2 + dh
    int dh = blk & 1;
    int o  = (blk >> 1) & 7;
    int bo = blk >> 1;             // b*8 + o
    int tid = threadIdx.x;

    for (int i = tid; i < GP2_TOT; i += 512) sp[i] = 0.f;
    if (tid < 54) sws[tid] = Ws[tid];
    __syncthreads();

    const float* src = g_pooled + (size_t)bo * 32768;
    int dbase = dh * 8 - 1;
    for (int i = tid; i < 2 * 10 * 1024; i += 512) {
        int px = i & 1023;
        int j  = (i >> 10) % 10;
        int p  = i / 10240;
        int dd = dbase + j;
        if ((unsigned)dd < 16u) {
            int u = px >> 5, v = px & 31;
            sp[p * GP2_CH + j * GP2_PLANE + (u + 1) * GP2_PITCH + (v + 1)] =
                src[p * 16384 + dd * 1024 + px];
        }
    }
    __syncthreads();

    // per-thread quads: q = k*512+tid, k=0..3
    int off0[4];
#pragma unroll
    for (int k = 0; k < 4; k++) {
        int q = k * 512 + tid;
        int v0 = (q & 7) * 4;
        int u  = (q >> 3) & 31;
        int dloc = q >> 8;
        off0[k] = dloc * GP2_PLANE + u * GP2_PITCH + v0;
    }

    float acc[4][4];
#pragma unroll
    for (int k = 0; k < 4; k++)
#pragma unroll
        for (int j = 0; j < 4; j++) acc[k][j] = 0.f;

#pragma unroll
    for (int p = 0; p < 2; p++) {
#pragma unroll
        for (int kd = 0; kd < 3; kd++) {
#pragma unroll
            for (int ku = 0; ku < 3; ku++) {
                const float* w = &sws[p * 27 + kd * 9 + ku * 3];
                float w0 = w[0], w1 = w[1], w2 = w[2];
                int base = p * GP2_CH + kd * GP2_PLANE + ku * GP2_PITCH;
#pragma unroll
                for (int k = 0; k < 4; k++) {
                    const float* rp = &sp[base + off0[k]];
                    float4 f = *(const float4*)rp;
                    float i4 = rp[4], i5 = rp[5];
                    acc[k][0] += w0 * f.x + w1 * f.y + w2 * f.z;
                    acc[k][1] += w0 * f.y + w1 * f.z + w2 * f.w;
                    acc[k][2] += w0 * f.z + w1 * f.w + w2 * i4;
                    acc[k][3] += w0 * f.w + w1 * i4 + w2 * i5;
                }
            }
        }
    }

    double ls = 0.0, lq = 0.0;
#pragma unroll
    for (int k = 0; k < 4; k++) {
        int q = k * 512 + tid;
        int v0 = (q & 7) * 4;
        int u  = (q >> 3) & 31;
        int dloc = q >> 8;
        float4 r; r.x = acc[k][0]; r.y = acc[k][1]; r.z = acc[k][2]; r.w = acc[k][3];
        *(float4*)&g_graw[(size_t)bo * 16384 + (size_t)(dh * 8 + dloc) * 1024 +
                          (size_t)u * 32 + v0] = r;
        ls += (double)(r.x + r.y + r.z + r.w);
        lq += (double)r.x * r.x + (double)r.y * r.y +
              (double)r.z * r.z + (double)r.w * r.w;
    }

    for (int off = 16; off; off >>= 1) {
        ls += __shfl_down_sync(0xffffffffu, ls, off);
        lq += __shfl_down_sync(0xffffffffu, lq, off);
    }
    int wid = tid >> 5, lane = tid & 31;
    if (lane == 0) { redA[wid] = ls; redB[wid] = lq; }
    __syncthreads();
    if (tid < 32) {
        double a = (tid < 16) ? redA[tid] : 0.0;
        double qq = (tid < 16) ? redB[tid] : 0.0;
        for (int off = 8; off; off >>= 1) {
            a += __shfl_down_sync(0xffffffffu, a, off);
            qq += __shfl_down_sync(0xffffffffu, qq, off);
        }
        if (tid == 0) {
            atomicAdd(&g_bnsum[o], a);
            atomicAdd(&g_bnsq[o], qq);
        }
    }
}

// ---------------- kernel 4: BN finalize ------------------------------------
__global__ void k_bnfin() {
    int o = threadIdx.x;
    if (o < COUT) {
        double N = (double)BATCH * DOUT * SS * SS;
        double mu = g_bnsum[o] / N;
        double var = g_bnsq[o] / N - mu * mu;
        g_bnmu[o]  = (float)mu;
        g_bninv[o] = (float)(1.0 / sqrt(var + (double)EPSV));
    }
}

// ---------------- kernel 5: scale + LayerNorm + transposed store -----------
__global__ __launch_bounds__(512) void k_final(
    const float* __restrict__ bng, const float* __restrict__ bnb,
    const float* __restrict__ lng, const float* __restrict__ lnb,
    float* __restrict__ out)
{
    __shared__ double redA[16], redB[16];
    __shared__ float bc[2];
    int blk = blockIdx.x;
    int b = blk >> 3, o = blk & 7;
    int tid = threadIdx.x;

    float mu = g_bnmu[o], inv = g_bninv[o];
    float ga = bng[0], be = bnb[0];
    const float* gr = g_graw   + (size_t)blk * 16384;
    const float* rt = g_routed + (size_t)blk * 16384;

    float xv[32];
    double ls = 0.0, lq = 0.0;
#pragma unroll
    for (int k = 0; k < 32; k++) {
        int i = k * 512 + tid;
        float g = (gr[i] - mu) * inv * ga + be;
        float sc = 1.f / (1.f + __expf(-g));
        float x = rt[i] * (1.f + sc);
        xv[k] = x;
        ls += x;
        lq += (double)x * x;
    }
    for (int off = 16; off; off >>= 1) {
        ls += __shfl_down_sync(0xffffffffu, ls, off);
        lq += __shfl_down_sync(0xffffffffu, lq, off);
    }
    int wid = tid >> 5, lane = tid & 31;
    if (lane == 0) { redA[wid] = ls; redB[wid] = lq; }
    __syncthreads();
    if (tid < 32) {
        double a = (tid < 16) ? redA[tid] : 0.0;
        double q = (tid < 16) ? redB[tid] : 0.0;
        for (int off = 8; off; off >>= 1) {
            a += __shfl_down_sync(0xffffffffu, a, off);
            q += __shfl_down_sync(0xffffffffu, q, off);
        }
        if (tid == 0) {
            double N = 16384.0;
            double mean = a / N;
            double var = q / N - mean * mean;
            bc[0] = (float)mean;
            bc[1] = (float)(1.0 / sqrt(var + (double)EPSV));
        }
    }
    __syncthreads();
    float mean = bc[0], rstd = bc[1];
    float* ob = out + ((size_t)o * BATCH + b) * 16384;
#pragma unroll
    for (int k = 0; k < 32; k++) {
        int i = k * 512 + tid;
        ob[i] = (xv[k] - mean) * rstd * lng[i] + lnb[i];
    }
}

// ---------------- launch ----------------------------------------------------
extern "C" void kernel_launch(void* const* d_in, const int* in_sizes, int n_in,
                              void* d_out, int out_size)
{
    const float* caps = (const float*)d_in[0];
    const float* Wt   = (const float*)d_in[1];
    const float* bt   = (const float*)d_in[2];
    const float* Wv   = (const float*)d_in[3];
    const float* bv   = (const float*)d_in[4];
    const float* Ws   = (const float*)d_in[5];
    const float* bng  = (const float*)d_in[6];
    const float* bnb  = (const float*)d_in[7];
    const float* lng  = (const float*)d_in[8];
    const float* lnb  = (const float*)d_in[9];
    float* out = (float*)d_out;

    cudaFuncSetAttribute(k_conv_mma, cudaFuncAttributeMaxDynamicSharedMemorySize, CONV_SMEM);
    cudaFuncSetAttribute(k_gate, cudaFuncAttributeMaxDynamicSharedMemorySize, GATE_SMEM);

    k_prep<<<9, 256>>>(Wt, bt, Wv, bv);

    dim3 gconv(8, BATCH);
    k_conv_mma<<<gconv, 256, CONV_SMEM>>>(caps);

    dim3 gval(64, COUT, BATCH);
    k_values<<<gval, 256>>>(Wv);

    k_gate<<<BATCH * COUT * 2, 512, GATE_SMEM>>>(Ws);

    k_bnfin<<<1, 8>>>();

    k_final<<<BATCH * COUT, 512>>>(bng, bnb, lng, lnb, out);

    (void)in_sizes; (void)n_in; (void)out_size;
}